// round 2
// baseline (speedup 1.0000x reference)
#include <cuda_runtime.h>
#include <cstdint>

// Problem constants
#define B_ROWS 8192
#define KDIM   2304     // 48*48
#define NDIM   128      // EMB_DIM
#define TM     64       // batch rows per CTA
#define KC     32       // K chunk
#define NCHUNK (KDIM / KC)   // 72
#define ALPHA  0.2f

// Padded smem strides (in 4-byte elements) for conflict-free fragment loads
#define SA_STRIDE 36    // 32 + 4  -> bank = 4*row + col  (distinct per lane)
#define SB_STRIDE 136   // 136 % 32 == 8 -> bank = 8*krow + ncol (distinct per lane)

__device__ __forceinline__ uint32_t f2tf32(float x) {
    uint32_t y;
    asm volatile("cvt.rna.tf32.f32 %0, %1;" : "=r"(y) : "f"(x));
    return y;
}

__device__ __forceinline__ void mma_tf32(float c[4], const uint32_t a[4], const uint32_t b[2]) {
    asm volatile(
        "mma.sync.aligned.m16n8k8.row.col.f32.tf32.tf32.f32 "
        "{%0,%1,%2,%3}, {%4,%5,%6,%7}, {%8,%9}, {%0,%1,%2,%3};"
        : "+f"(c[0]), "+f"(c[1]), "+f"(c[2]), "+f"(c[3])
        : "r"(a[0]), "r"(a[1]), "r"(a[2]), "r"(a[3]), "r"(b[0]), "r"(b[1]));
}

__global__ void zero_out_kernel(float* out) { out[0] = 0.0f; }

__global__ __launch_bounds__(256, 1)
void triplet_kernel(const float* __restrict__ gA,
                    const float* __restrict__ gP,
                    const float* __restrict__ gN,
                    const float* __restrict__ gW,
                    float* __restrict__ out)
{
    __shared__ uint32_t sA[128 * SA_STRIDE];   // 64 ap-diff rows + 64 an-diff rows, tf32
    __shared__ uint32_t sB[KC * SB_STRIDE];    // W chunk [KC x 128], tf32
    __shared__ float    sD[128];               // per-row squared norms

    const int t    = threadIdx.x;
    const int warp = t >> 5;
    const int lane = t & 31;
    const int warpM = warp & 3;   // 4 warps along M (32 rows each)
    const int warpN = warp >> 2;  // 2 warps along N (64 cols each)
    const int r0    = blockIdx.x * TM;

    // Accumulators: 2 m-tiles (16 rows) x 8 n-tiles (8 cols) x 4 regs
    float acc[2][8][4];
#pragma unroll
    for (int mt = 0; mt < 2; ++mt)
#pragma unroll
        for (int nt = 0; nt < 8; ++nt)
#pragma unroll
            for (int i = 0; i < 4; ++i) acc[mt][nt][i] = 0.0f;

    // Per-thread gmem tile assignment
    // A/P/N: 64 rows x 8 float4 -> 512 items, 2 per thread
    // W:     32 rows x 32 float4 -> 1024 items, 4 per thread
    int aRow[2], aC4[2];
#pragma unroll
    for (int i = 0; i < 2; ++i) {
        int idx = i * 256 + t;
        aRow[i] = idx >> 3;
        aC4[i]  = idx & 7;
    }
    int wRow[4], wC4[4];
#pragma unroll
    for (int i = 0; i < 4; ++i) {
        int idx = i * 256 + t;
        wRow[i] = idx >> 5;
        wC4[i]  = idx & 31;
    }

    float4 ra[2], rp[2], rn[2], rw[4];

    // ---- prefetch chunk 0 ----
    {
        const int k0 = 0;
#pragma unroll
        for (int i = 0; i < 2; ++i) {
            size_t off = (size_t)(r0 + aRow[i]) * KDIM + k0 + aC4[i] * 4;
            ra[i] = *(const float4*)(gA + off);
            rp[i] = *(const float4*)(gP + off);
            rn[i] = *(const float4*)(gN + off);
        }
#pragma unroll
        for (int i = 0; i < 4; ++i) {
            size_t off = (size_t)(k0 + wRow[i]) * NDIM + wC4[i] * 4;
            rw[i] = *(const float4*)(gW + off);
        }
    }

#pragma unroll 1
    for (int c = 0; c < NCHUNK; ++c) {
        __syncthreads();   // previous chunk's compute done; smem free

        // store diffs (tf32) and W chunk (tf32) into smem
#pragma unroll
        for (int i = 0; i < 2; ++i) {
            int row = aRow[i];
            int col = aC4[i] * 4;
            uint32_t* ap = &sA[row * SA_STRIDE + col];
            uint32_t* an = &sA[(64 + row) * SA_STRIDE + col];
            ap[0] = f2tf32(ra[i].x - rp[i].x);
            ap[1] = f2tf32(ra[i].y - rp[i].y);
            ap[2] = f2tf32(ra[i].z - rp[i].z);
            ap[3] = f2tf32(ra[i].w - rp[i].w);
            an[0] = f2tf32(ra[i].x - rn[i].x);
            an[1] = f2tf32(ra[i].y - rn[i].y);
            an[2] = f2tf32(ra[i].z - rn[i].z);
            an[3] = f2tf32(ra[i].w - rn[i].w);
        }
#pragma unroll
        for (int i = 0; i < 4; ++i) {
            uint32_t* wp = &sB[wRow[i] * SB_STRIDE + wC4[i] * 4];
            wp[0] = f2tf32(rw[i].x);
            wp[1] = f2tf32(rw[i].y);
            wp[2] = f2tf32(rw[i].z);
            wp[3] = f2tf32(rw[i].w);
        }

        // prefetch next chunk while this one computes
        if (c + 1 < NCHUNK) {
            const int k0 = (c + 1) * KC;
#pragma unroll
            for (int i = 0; i < 2; ++i) {
                size_t off = (size_t)(r0 + aRow[i]) * KDIM + k0 + aC4[i] * 4;
                ra[i] = *(const float4*)(gA + off);
                rp[i] = *(const float4*)(gP + off);
                rn[i] = *(const float4*)(gN + off);
            }
#pragma unroll
            for (int i = 0; i < 4; ++i) {
                size_t off = (size_t)(k0 + wRow[i]) * NDIM + wC4[i] * 4;
                rw[i] = *(const float4*)(gW + off);
            }
        }

        __syncthreads();   // smem tiles ready

        // compute: 4 k-substeps of 8
#pragma unroll
        for (int k8 = 0; k8 < 4; ++k8) {
            uint32_t af[2][4];
#pragma unroll
            for (int mt = 0; mt < 2; ++mt) {
                int row = warpM * 32 + mt * 16 + (lane >> 2);
                int col = k8 * 8 + (lane & 3);
                af[mt][0] = sA[row * SA_STRIDE + col];
                af[mt][1] = sA[(row + 8) * SA_STRIDE + col];
                af[mt][2] = sA[row * SA_STRIDE + col + 4];
                af[mt][3] = sA[(row + 8) * SA_STRIDE + col + 4];
            }
            uint32_t bf[8][2];
#pragma unroll
            for (int nt = 0; nt < 8; ++nt) {
                int ncol = warpN * 64 + nt * 8 + (lane >> 2);
                int krow = k8 * 8 + (lane & 3);
                bf[nt][0] = sB[krow * SB_STRIDE + ncol];
                bf[nt][1] = sB[(krow + 4) * SB_STRIDE + ncol];
            }
#pragma unroll
            for (int mt = 0; mt < 2; ++mt)
#pragma unroll
                for (int nt = 0; nt < 8; ++nt)
                    mma_tf32(acc[mt][nt], af[mt], bf[nt]);
        }
    }

    // ---- epilogue: per-row sum of squares over N=128 ----
    __syncthreads();
    if (t < 128) sD[t] = 0.0f;
    __syncthreads();

#pragma unroll
    for (int mt = 0; mt < 2; ++mt) {
        int row = warpM * 32 + mt * 16 + (lane >> 2);
        float s0 = 0.0f, s1 = 0.0f;
#pragma unroll
        for (int nt = 0; nt < 8; ++nt) {
            s0 += acc[mt][nt][0] * acc[mt][nt][0] + acc[mt][nt][1] * acc[mt][nt][1];
            s1 += acc[mt][nt][2] * acc[mt][nt][2] + acc[mt][nt][3] * acc[mt][nt][3];
        }
        // reduce across the quad (lane&3 covers the N columns)
        s0 += __shfl_xor_sync(0xffffffff, s0, 1);
        s0 += __shfl_xor_sync(0xffffffff, s0, 2);
        s1 += __shfl_xor_sync(0xffffffff, s1, 1);
        s1 += __shfl_xor_sync(0xffffffff, s1, 2);
        if ((lane & 3) == 0) {
            atomicAdd(&sD[row], s0);        // 2 warpN warps contribute each row
            atomicAdd(&sD[row + 8], s1);
        }
    }
    __syncthreads();

    if (t < 64) {
        float d_ap = sD[t];
        float d_an = sD[64 + t];
        float loss = fmaxf(d_ap - d_an + ALPHA, 0.0f);
#pragma unroll
        for (int off = 16; off > 0; off >>= 1)
            loss += __shfl_xor_sync(0xffffffff, loss, off);
        if ((t & 31) == 0)
            atomicAdd(out, loss * (1.0f / (float)B_ROWS));
    }
}

extern "C" void kernel_launch(void* const* d_in, const int* in_sizes, int n_in,
                              void* d_out, int out_size)
{
    const float* a = (const float*)d_in[0];  // batch_anchor [8192,1,48,48]
    const float* p = (const float*)d_in[1];  // batch_pos
    const float* n = (const float*)d_in[2];  // batch_neg
    const float* w = (const float*)d_in[3];  // W [2304,128]
    // d_in[4] = b, cancels in the differences; unused
    float* out = (float*)d_out;

    zero_out_kernel<<<1, 1>>>(out);
    triplet_kernel<<<B_ROWS / TM, 256>>>(a, p, n, w, out);
}